// round 1
// baseline (speedup 1.0000x reference)
#include <cuda_runtime.h>
#include <math.h>

// GeneralMaxValPool: segment-argmax pooling over COO remap.
// B=4, OLD=262144, NEW=65536, V=64, nnz=262144, BV=256.

#define OLDN 262144
#define NEWN 65536
#define BB   4
#define VV   64
#define BVN  256
#define NNZ  262144
#define SEGS 32          // segments per block
#define PITCH 257        // shared pitch (odd -> conflict-free transposed access)

__device__ int g_start[NEWN + 1];

__global__ void seg_start_kernel(const int* __restrict__ row) {
    int i = blockIdx.x * blockDim.x + threadIdx.x;
    if (i >= NNZ) return;
    int r = row[i];
    if (i == 0) {
        g_start[r] = 0;
    } else {
        int rp = row[i - 1];
        if (r != rp) g_start[r] = i;   // row dense+sorted: every segment appears
    }
    if (i == NNZ - 1) g_start[NEWN] = NNZ;
}

__global__ void __launch_bounds__(256)
pool_kernel(const float* __restrict__ x,
            const float* __restrict__ weights,
            const int*   __restrict__ col,
            float* __restrict__ out)
{
    extern __shared__ float smem[];
    float* sval = smem;                               // [SEGS][PITCH]
    int*   srow = (int*)(smem + SEGS * PITCH);        // [SEGS][PITCH]

    const int s0 = blockIdx.x * SEGS;
    const int t  = threadIdx.x;
    const int b  = t >> 6;        // 0..3
    const int v  = t & 63;        // 0..63

    // Phase 1: per-segment argmax. Thread t handles flat column (b,v).
    // 64-thread groups read 256B-contiguous rows of x -> fully coalesced.
    for (int sl = 0; sl < SEGS; ++sl) {
        const int s  = s0 + sl;
        const int i0 = g_start[s];
        const int i1 = g_start[s + 1];
        float bestw   = -INFINITY;
        float bestval = 0.0f;
        int   bestn   = 0;
        for (int i = i0; i < i1; ++i) {
            const int   n   = __ldg(&col[i]);
            const float w   = __ldg(&weights[i]);
            const float val = __ldg(&x[(size_t)b * (OLDN * VV) + (size_t)n * VV + v]);
            const float wv  = w * val;
            if (wv > bestw) { bestw = wv; bestval = val; bestn = n; }  // strict > == min-index tiebreak
        }
        sval[sl * PITCH + t] = bestval;
        srow[sl * PITCH + t] = bestn;
    }
    __syncthreads();

    // Phase 2a: x_pooled[b, s, v] -> out[b*NEW*V + s*V + v], coalesced.
    for (int b2 = 0; b2 < BB; ++b2) {
        #pragma unroll
        for (int iter = 0; iter < (SEGS * VV) / 256; ++iter) {   // 8 iters
            const int idx = iter * 256 + t;                      // 0..2047
            const int sl  = idx >> 6;
            const int v2  = idx & 63;
            out[(size_t)b2 * (NEWN * VV) + (size_t)(s0 + sl) * VV + v2] =
                sval[sl * PITCH + b2 * 64 + v2];
        }
    }

    // Phase 2b: nnz_ind. out[OFF1 + c*NEW + s] = argmax old-node; out[OFF2 + ...] = c.
    // Each warp writes 32 consecutive s for one c -> 128B coalesced stores.
    const size_t OFF1 = (size_t)BB * NEWN * VV;            // 16,777,216
    const size_t OFF2 = OFF1 + (size_t)BVN * NEWN;         // 33,554,432
    #pragma unroll
    for (int iter = 0; iter < (BVN * SEGS) / 256; ++iter) {  // 32 iters
        const int idx = iter * 256 + t;                       // 0..8191
        const int c   = idx >> 5;                             // 0..255
        const int sl  = idx & 31;
        const int cb  = c & 3;                                // c = v*B + b
        const int cv  = c >> 2;
        const int tc  = cb * 64 + cv;                         // thread-col of (b,v)
        const size_t o = (size_t)c * NEWN + (size_t)(s0 + sl);
        out[OFF1 + o] = (float)srow[sl * PITCH + tc];
        out[OFF2 + o] = (float)c;
    }
}

extern "C" void kernel_launch(void* const* d_in, const int* in_sizes, int n_in,
                              void* d_out, int out_size) {
    const float* x       = (const float*)d_in[0];
    const float* weights = (const float*)d_in[1];
    const int*   row     = (const int*)d_in[2];
    const int*   col     = (const int*)d_in[3];
    float* out = (float*)d_out;

    static const size_t SMEM = (size_t)SEGS * PITCH * 4 * 2;   // 65,792 B
    cudaFuncSetAttribute(pool_kernel, cudaFuncAttributeMaxDynamicSharedMemorySize, (int)SMEM);

    seg_start_kernel<<<NNZ / 256, 256>>>(row);
    pool_kernel<<<NEWN / SEGS, 256, SMEM>>>(x, weights, col, out);
}